// round 1
// baseline (speedup 1.0000x reference)
#include <cuda_runtime.h>
#include <cuda_bf16.h>

// Problem constants
// B=8, N=1024, D=768, H=12, Hd=64
// qkv scratch:  [8192, 2304]  (q | k | v interleaved per row as in W_qkv layout)
// attn scratch: [8192, 768]   ([B, N, H, Hd] == [B, N, D] after head merge)

__device__ float g_qkv[8192 * 2304];   // ~75.5 MB
__device__ float g_attn[8192 * 768];   // ~25 MB

// ---------------------------------------------------------------------------
// SGEMM: C[M,N] = A[M,K] @ W[N,K]^T + bias[N]
// BM=BN=128, BK=8, 256 threads, 8x8 interleaved micro-tiles (stride-16),
// conflict-free smem reads, float4 global loads. All dims divide tiles exactly
// for this problem (M=8192, N in {2304,768}, K=768).
// ---------------------------------------------------------------------------
__global__ __launch_bounds__(256) void sgemm_bias_kernel(
    const float* __restrict__ A, const float* __restrict__ W,
    const float* __restrict__ bias, float* __restrict__ C,
    int M, int N, int K)
{
    constexpr int BM = 128, BN = 128, BK = 8, TM = 8, TN = 8;
    __shared__ float As[BK][BM];
    __shared__ float Ws[BK][BN];

    const int tid  = threadIdx.x;
    const int m0   = blockIdx.y * BM;
    const int n0   = blockIdx.x * BN;
    const int tCol = tid & 15;   // 0..15
    const int tRow = tid >> 4;   // 0..15

    // Global-load mapping: 1 float4 per thread per operand per BK-step
    const int ldRow = tid >> 1;        // 0..127
    const int ldCol = (tid & 1) * 4;   // 0 or 4

    const float* Aptr = A + (size_t)(m0 + ldRow) * K + ldCol;
    const float* Wptr = W + (size_t)(n0 + ldRow) * K + ldCol;

    float acc[TM][TN];
    #pragma unroll
    for (int i = 0; i < TM; i++)
        #pragma unroll
        for (int j = 0; j < TN; j++)
            acc[i][j] = 0.0f;

    for (int k0 = 0; k0 < K; k0 += BK) {
        float4 av = *(const float4*)(Aptr + k0);
        float4 wv = *(const float4*)(Wptr + k0);
        As[ldCol + 0][ldRow] = av.x;
        As[ldCol + 1][ldRow] = av.y;
        As[ldCol + 2][ldRow] = av.z;
        As[ldCol + 3][ldRow] = av.w;
        Ws[ldCol + 0][ldRow] = wv.x;
        Ws[ldCol + 1][ldRow] = wv.y;
        Ws[ldCol + 2][ldRow] = wv.z;
        Ws[ldCol + 3][ldRow] = wv.w;
        __syncthreads();

        #pragma unroll
        for (int k = 0; k < BK; k++) {
            float rm[TM], rn[TN];
            #pragma unroll
            for (int i = 0; i < TM; i++) rm[i] = As[k][tRow + i * 16];
            #pragma unroll
            for (int j = 0; j < TN; j++) rn[j] = Ws[k][tCol + j * 16];
            #pragma unroll
            for (int i = 0; i < TM; i++)
                #pragma unroll
                for (int j = 0; j < TN; j++)
                    acc[i][j] += rm[i] * rn[j];
        }
        __syncthreads();
    }

    #pragma unroll
    for (int j = 0; j < TN; j++) {
        const int n = n0 + tCol + j * 16;
        const float bv = bias[n];
        #pragma unroll
        for (int i = 0; i < TM; i++) {
            const int m = m0 + tRow + i * 16;
            C[(size_t)m * N + n] = acc[i][j] + bv;
        }
    }
}

// ---------------------------------------------------------------------------
// Flash attention (fp32): 1 thread = 1 query. Block = 128 threads = 128
// queries of one (b, h). K/V streamed through smem in 64-key tiles; all
// threads in a warp read the same K/V row -> pure smem broadcast.
// Online softmax: rescale o[] only when the running max changes.
// ---------------------------------------------------------------------------
__global__ __launch_bounds__(128) void attn_kernel()
{
    __shared__ float4 Ks[64][16];
    __shared__ float4 Vs[64][16];

    const int tid   = threadIdx.x;
    const int qtile = blockIdx.x & 7;         // 8 q-tiles of 128
    const int bh    = blockIdx.x >> 3;        // 0..95
    const int h     = bh % 12;
    const int b     = bh / 12;
    const int n     = qtile * 128 + tid;      // query index within sequence

    const int rowQ  = (b * 1024 + n) * 2304;

    float q[64];
    {
        const float4* qp = (const float4*)&g_qkv[rowQ + h * 64];
        #pragma unroll
        for (int c = 0; c < 16; c++) {
            float4 t = qp[c];
            q[4 * c + 0] = t.x; q[4 * c + 1] = t.y;
            q[4 * c + 2] = t.z; q[4 * c + 3] = t.w;
        }
    }

    float o[64];
    #pragma unroll
    for (int d = 0; d < 64; d++) o[d] = 0.0f;
    float m = -1e30f, l = 0.0f;
    const float scale = 0.125f;   // 1/sqrt(64)

    for (int kt = 0; kt < 1024; kt += 64) {
        __syncthreads();
        // Cooperative load of K/V tile: 64 rows x 16 float4 each, 128 threads
        #pragma unroll
        for (int it = 0; it < 8; it++) {
            const int idx = tid + it * 128;
            const int row = idx >> 4;
            const int c   = idx & 15;
            const int base = (b * 1024 + kt + row) * 2304 + h * 64 + 4 * c;
            Ks[row][c] = *(const float4*)&g_qkv[base + 768];
            Vs[row][c] = *(const float4*)&g_qkv[base + 1536];
        }
        __syncthreads();

        for (int j = 0; j < 64; j++) {
            float s = 0.0f;
            #pragma unroll
            for (int c = 0; c < 16; c++) {
                float4 kv = Ks[j][c];
                s += q[4 * c + 0] * kv.x + q[4 * c + 1] * kv.y
                   + q[4 * c + 2] * kv.z + q[4 * c + 3] * kv.w;
            }
            s *= scale;
            if (s > m) {
                const float corr = __expf(m - s);
                l *= corr;
                #pragma unroll
                for (int d = 0; d < 64; d++) o[d] *= corr;
                m = s;
            }
            const float p = __expf(s - m);
            l += p;
            #pragma unroll
            for (int c = 0; c < 16; c++) {
                float4 vv = Vs[j][c];
                o[4 * c + 0] += p * vv.x;
                o[4 * c + 1] += p * vv.y;
                o[4 * c + 2] += p * vv.z;
                o[4 * c + 3] += p * vv.w;
            }
        }
    }

    const float inv = 1.0f / l;
    float4* op = (float4*)&g_attn[(b * 1024 + n) * 768 + h * 64];
    #pragma unroll
    for (int c = 0; c < 16; c++) {
        op[c] = make_float4(o[4 * c + 0] * inv, o[4 * c + 1] * inv,
                            o[4 * c + 2] * inv, o[4 * c + 3] * inv);
    }
}

// ---------------------------------------------------------------------------
// Launch
// ---------------------------------------------------------------------------
extern "C" void kernel_launch(void* const* d_in, const int* in_sizes, int n_in,
                              void* d_out, int out_size)
{
    const float* x     = (const float*)d_in[0];   // [8, 1024, 768]
    const float* Wqkv  = (const float*)d_in[1];   // [2304, 768]
    const float* bqkv  = (const float*)d_in[2];   // [2304]
    const float* Wproj = (const float*)d_in[3];   // [768, 768]
    const float* bproj = (const float*)d_in[4];   // [768]
    float* out = (float*)d_out;                   // [8, 1024, 768]

    float* qkv;
    float* attn;
    cudaGetSymbolAddress((void**)&qkv,  g_qkv);
    cudaGetSymbolAddress((void**)&attn, g_attn);

    // 1) QKV projection: [8192,768] @ [2304,768]^T + b -> [8192,2304]
    {
        dim3 grid(2304 / 128, 8192 / 128);
        sgemm_bias_kernel<<<grid, 256>>>(x, Wqkv, bqkv, qkv, 8192, 2304, 768);
    }

    // 2) Attention: per (b,h), softmax(QK^T/8) V -> [8192, 768]
    {
        attn_kernel<<<768, 128>>>();
    }

    // 3) Output projection: [8192,768] @ [768,768]^T + b -> d_out
    {
        dim3 grid(768 / 128, 8192 / 128);
        sgemm_bias_kernel<<<grid, 256>>>(attn, Wproj, bproj, out, 8192, 768, 768);
    }
}

// round 2
// speedup vs baseline: 3.6352x; 3.6352x over previous
#include <cuda_runtime.h>
#include <cuda_bf16.h>
#include <cstdint>

// Problem: B=8, N=1024, D=768, H=12, Hd=64
// qkv scratch:  [8192, 2304]  (row = token, cols = [q|k|v] as in W_qkv layout)
// attn scratch: [8192, 768]

__device__ float g_qkv[8192 * 2304];
__device__ float g_attn[8192 * 768];

// ---------------------------------------------------------------------------
// helpers
// ---------------------------------------------------------------------------
__device__ __forceinline__ uint32_t f2tf(float f) {
    uint32_t u;
    asm("cvt.rna.tf32.f32 %0, %1;" : "=r"(u) : "f"(f));
    return u;
}

__device__ __forceinline__ void mma_tf32(float c[4],
                                         uint32_t a0, uint32_t a1, uint32_t a2, uint32_t a3,
                                         uint32_t b0, uint32_t b1) {
    asm volatile(
        "mma.sync.aligned.m16n8k8.row.col.f32.tf32.tf32.f32 "
        "{%0,%1,%2,%3}, {%4,%5,%6,%7}, {%8,%9}, {%0,%1,%2,%3};"
        : "+f"(c[0]), "+f"(c[1]), "+f"(c[2]), "+f"(c[3])
        : "r"(a0), "r"(a1), "r"(a2), "r"(a3), "r"(b0), "r"(b1));
}

// ---------------------------------------------------------------------------
// TF32 GEMM: C[M,N] = A[M,K] @ W[N,K]^T + bias[N]
// Block 128x128, BK=32, 256 threads (8 warps as 4x2), warp tile 32x64.
// smem stores tf32 bit patterns, row-major [m][k] / [n][k] with +4 pad.
// ---------------------------------------------------------------------------
__global__ __launch_bounds__(256) void gemm_tf32_kernel(
    const float* __restrict__ A, const float* __restrict__ W,
    const float* __restrict__ bias, float* __restrict__ C,
    int M, int N, int K)
{
    constexpr int LDA = 36;  // 32 + 4 pad
    __shared__ uint32_t As[128 * LDA];
    __shared__ uint32_t Ws[128 * LDA];

    const int tid  = threadIdx.x;
    const int lane = tid & 31;
    const int wrp  = tid >> 5;
    const int wm   = wrp & 3;     // 4 warp-rows (32 m each)
    const int wn   = wrp >> 2;    // 2 warp-cols (64 n each)
    const int g    = lane >> 2;   // groupID
    const int tig  = lane & 3;    // thread-in-group

    const int m0 = blockIdx.y * 128;
    const int n0 = blockIdx.x * 128;

    // global load mapping: 4 float4 per operand per BK-block
    const int lr  = tid >> 3;          // 0..31
    const int lc4 = (tid & 7) * 4;     // 0,4,...,28

    float acc[2][8][4];
    #pragma unroll
    for (int i = 0; i < 2; i++)
        #pragma unroll
        for (int j = 0; j < 8; j++)
            #pragma unroll
            for (int c = 0; c < 4; c++) acc[i][j][c] = 0.0f;

    float4 ra[4], rw[4];
    #pragma unroll
    for (int i = 0; i < 4; i++) {
        const int row = lr + 32 * i;
        ra[i] = *(const float4*)&A[(size_t)(m0 + row) * K + lc4];
        rw[i] = *(const float4*)&W[(size_t)(n0 + row) * K + lc4];
    }

    for (int kt = 0; kt < K; kt += 32) {
        __syncthreads();
        #pragma unroll
        for (int i = 0; i < 4; i++) {
            const int row = lr + 32 * i;
            *(uint4*)&As[row * LDA + lc4] =
                make_uint4(f2tf(ra[i].x), f2tf(ra[i].y), f2tf(ra[i].z), f2tf(ra[i].w));
            *(uint4*)&Ws[row * LDA + lc4] =
                make_uint4(f2tf(rw[i].x), f2tf(rw[i].y), f2tf(rw[i].z), f2tf(rw[i].w));
        }
        __syncthreads();

        if (kt + 32 < K) {
            #pragma unroll
            for (int i = 0; i < 4; i++) {
                const int row = lr + 32 * i;
                ra[i] = *(const float4*)&A[(size_t)(m0 + row) * K + kt + 32 + lc4];
                rw[i] = *(const float4*)&W[(size_t)(n0 + row) * K + kt + 32 + lc4];
            }
        }

        #pragma unroll
        for (int ks = 0; ks < 4; ks++) {
            const int kc = ks * 8;
            uint32_t a[2][4];
            #pragma unroll
            for (int i = 0; i < 2; i++) {
                const int rb = 32 * wm + 16 * i;
                a[i][0] = As[(rb + g) * LDA + kc + tig];
                a[i][1] = As[(rb + g + 8) * LDA + kc + tig];
                a[i][2] = As[(rb + g) * LDA + kc + tig + 4];
                a[i][3] = As[(rb + g + 8) * LDA + kc + tig + 4];
            }
            #pragma unroll
            for (int j = 0; j < 8; j++) {
                const int nb = 64 * wn + 8 * j;
                const uint32_t b0 = Ws[(nb + g) * LDA + kc + tig];
                const uint32_t b1 = Ws[(nb + g) * LDA + kc + tig + 4];
                mma_tf32(acc[0][j], a[0][0], a[0][1], a[0][2], a[0][3], b0, b1);
                mma_tf32(acc[1][j], a[1][0], a[1][1], a[1][2], a[1][3], b0, b1);
            }
        }
    }

    // epilogue: bias + store (float2 per row-half)
    #pragma unroll
    for (int j = 0; j < 8; j++) {
        const int col = n0 + 64 * wn + 8 * j + 2 * tig;
        const float b0 = bias[col];
        const float b1 = bias[col + 1];
        #pragma unroll
        for (int i = 0; i < 2; i++) {
            const int row = m0 + 32 * wm + 16 * i + g;
            *(float2*)&C[(size_t)row * N + col] =
                make_float2(acc[i][j][0] + b0, acc[i][j][1] + b1);
            *(float2*)&C[(size_t)(row + 8) * N + col] =
                make_float2(acc[i][j][2] + b0, acc[i][j][3] + b1);
        }
    }
}

// ---------------------------------------------------------------------------
// TF32 flash attention.
// Block: 128 queries of one (b,h), 128 threads (4 warps x 32 q-rows).
// Key tiles of 64. S = Q@K^T via mma; online softmax in registers (quad shfl
// reductions); P written to smem as tf32 -> A-frags for P@V; V transposed in
// smem for conflict-free B-frags.
// Dynamic smem: Qs[128][68] Ks[64][68] Vt[64][68] Ps[128][68] (u32 tf32 bits)
// ---------------------------------------------------------------------------
__global__ __launch_bounds__(128) void attn_tf32_kernel()
{
    extern __shared__ uint32_t smem[];
    uint32_t* Qs = smem;                 // 128*68
    uint32_t* Ks = Qs + 128 * 68;        // 64*68
    uint32_t* Vt = Ks + 64 * 68;         // 64*68  (transposed: [hd][key])
    uint32_t* Ps = Vt + 64 * 68;         // 128*68

    const int tid  = threadIdx.x;
    const int lane = tid & 31;
    const int wrp  = tid >> 5;
    const int g    = lane >> 2;
    const int tig  = lane & 3;

    const int qtile = blockIdx.x & 7;
    const int bh    = blockIdx.x >> 3;
    const int h     = bh % 12;
    const int b     = bh / 12;
    const int q0    = qtile * 128;

    // load Q tile [128][64] -> tf32 smem
    #pragma unroll
    for (int it = 0; it < 16; it++) {
        const int e   = tid + it * 128;
        const int row = e >> 4;
        const int c4  = (e & 15) * 4;
        const float4 qv = *(const float4*)&g_qkv[(size_t)(b * 1024 + q0 + row) * 2304 + h * 64 + c4];
        *(uint4*)&Qs[row * 68 + c4] = make_uint4(f2tf(qv.x), f2tf(qv.y), f2tf(qv.z), f2tf(qv.w));
    }

    float O[2][8][4];
    #pragma unroll
    for (int i = 0; i < 2; i++)
        #pragma unroll
        for (int j = 0; j < 8; j++)
            #pragma unroll
            for (int c = 0; c < 4; c++) O[i][j][c] = 0.0f;

    float mrun[2][2], lrun[2][2];
    #pragma unroll
    for (int i = 0; i < 2; i++)
        #pragma unroll
        for (int hf = 0; hf < 2; hf++) { mrun[i][hf] = -1e30f; lrun[i][hf] = 0.0f; }

    const int mb = 32 * wrp;  // warp's q-row base within tile

    for (int kt = 0; kt < 1024; kt += 64) {
        __syncthreads();
        // load K [64][64] and V (transposed) tiles
        #pragma unroll
        for (int it = 0; it < 8; it++) {
            const int e   = tid + it * 128;
            const int key = e >> 4;
            const int c4  = (e & 15) * 4;
            const size_t base = (size_t)(b * 1024 + kt + key) * 2304 + h * 64 + c4;
            const float4 kv = *(const float4*)&g_qkv[base + 768];
            *(uint4*)&Ks[key * 68 + c4] = make_uint4(f2tf(kv.x), f2tf(kv.y), f2tf(kv.z), f2tf(kv.w));
            const float4 vv = *(const float4*)&g_qkv[base + 1536];
            Vt[(c4 + 0) * 68 + key] = f2tf(vv.x);
            Vt[(c4 + 1) * 68 + key] = f2tf(vv.y);
            Vt[(c4 + 2) * 68 + key] = f2tf(vv.z);
            Vt[(c4 + 3) * 68 + key] = f2tf(vv.w);
        }
        __syncthreads();

        // S = Q @ K^T  (k-dim = hd = 64)
        float s[2][8][4];
        #pragma unroll
        for (int i = 0; i < 2; i++)
            #pragma unroll
            for (int j = 0; j < 8; j++)
                #pragma unroll
                for (int c = 0; c < 4; c++) s[i][j][c] = 0.0f;

        #pragma unroll
        for (int ks = 0; ks < 8; ks++) {
            const int kc = ks * 8;
            uint32_t a[2][4];
            #pragma unroll
            for (int i = 0; i < 2; i++) {
                const int rb = mb + 16 * i;
                a[i][0] = Qs[(rb + g) * 68 + kc + tig];
                a[i][1] = Qs[(rb + g + 8) * 68 + kc + tig];
                a[i][2] = Qs[(rb + g) * 68 + kc + tig + 4];
                a[i][3] = Qs[(rb + g + 8) * 68 + kc + tig + 4];
            }
            #pragma unroll
            for (int j = 0; j < 8; j++) {
                const uint32_t b0 = Ks[(8 * j + g) * 68 + kc + tig];
                const uint32_t b1 = Ks[(8 * j + g) * 68 + kc + tig + 4];
                mma_tf32(s[0][j], a[0][0], a[0][1], a[0][2], a[0][3], b0, b1);
                mma_tf32(s[1][j], a[1][0], a[1][1], a[1][2], a[1][3], b0, b1);
            }
        }

        // online softmax (scale 1/8) + write P to Ps as tf32
        #pragma unroll
        for (int i = 0; i < 2; i++) {
            #pragma unroll
            for (int hf = 0; hf < 2; hf++) {
                float mx = -1e30f;
                #pragma unroll
                for (int j = 0; j < 8; j++) {
                    s[i][j][2 * hf]     *= 0.125f;
                    s[i][j][2 * hf + 1] *= 0.125f;
                    mx = fmaxf(mx, fmaxf(s[i][j][2 * hf], s[i][j][2 * hf + 1]));
                }
                mx = fmaxf(mx, __shfl_xor_sync(0xffffffffu, mx, 1));
                mx = fmaxf(mx, __shfl_xor_sync(0xffffffffu, mx, 2));
                const float nm   = fmaxf(mrun[i][hf], mx);
                const float corr = __expf(mrun[i][hf] - nm);
                mrun[i][hf] = nm;
                float sum = 0.0f;
                #pragma unroll
                for (int j = 0; j < 8; j++) {
                    const float p0 = __expf(s[i][j][2 * hf] - nm);
                    const float p1 = __expf(s[i][j][2 * hf + 1] - nm);
                    s[i][j][2 * hf] = p0;
                    s[i][j][2 * hf + 1] = p1;
                    sum += p0 + p1;
                }
                sum += __shfl_xor_sync(0xffffffffu, sum, 1);
                sum += __shfl_xor_sync(0xffffffffu, sum, 2);
                lrun[i][hf] = lrun[i][hf] * corr + sum;
                #pragma unroll
                for (int j = 0; j < 8; j++) {
                    O[i][j][2 * hf]     *= corr;
                    O[i][j][2 * hf + 1] *= corr;
                }
                // write this half-row's P values
                const int row = mb + 16 * i + g + 8 * hf;
                #pragma unroll
                for (int j = 0; j < 8; j++) {
                    *(uint2*)&Ps[row * 68 + 8 * j + 2 * tig] =
                        make_uint2(f2tf(s[i][j][2 * hf]), f2tf(s[i][j][2 * hf + 1]));
                }
            }
        }
        __syncwarp();

        // O += P @ V  (k-dim = key = 64); A from Ps, B from Vt
        #pragma unroll
        for (int ks = 0; ks < 8; ks++) {
            const int kc = ks * 8;
            uint32_t a[2][4];
            #pragma unroll
            for (int i = 0; i < 2; i++) {
                const int rb = mb + 16 * i;
                a[i][0] = Ps[(rb + g) * 68 + kc + tig];
                a[i][1] = Ps[(rb + g + 8) * 68 + kc + tig];
                a[i][2] = Ps[(rb + g) * 68 + kc + tig + 4];
                a[i][3] = Ps[(rb + g + 8) * 68 + kc + tig + 4];
            }
            #pragma unroll
            for (int j = 0; j < 8; j++) {
                const uint32_t b0 = Vt[(8 * j + g) * 68 + kc + tig];
                const uint32_t b1 = Vt[(8 * j + g) * 68 + kc + tig + 4];
                mma_tf32(O[0][j], a[0][0], a[0][1], a[0][2], a[0][3], b0, b1);
                mma_tf32(O[1][j], a[1][0], a[1][1], a[1][2], a[1][3], b0, b1);
            }
        }
    }

    // normalize + store
    #pragma unroll
    for (int i = 0; i < 2; i++) {
        #pragma unroll
        for (int hf = 0; hf < 2; hf++) {
            const float linv = 1.0f / lrun[i][hf];
            const int row = q0 + mb + 16 * i + g + 8 * hf;
            #pragma unroll
            for (int j = 0; j < 8; j++) {
                const int col = h * 64 + 8 * j + 2 * tig;
                *(float2*)&g_attn[(size_t)(b * 1024 + row) * 768 + col] =
                    make_float2(O[i][j][2 * hf] * linv, O[i][j][2 * hf + 1] * linv);
            }
        }
    }
}

// ---------------------------------------------------------------------------
// Launch
// ---------------------------------------------------------------------------
extern "C" void kernel_launch(void* const* d_in, const int* in_sizes, int n_in,
                              void* d_out, int out_size)
{
    const float* x     = (const float*)d_in[0];
    const float* Wqkv  = (const float*)d_in[1];
    const float* bqkv  = (const float*)d_in[2];
    const float* Wproj = (const float*)d_in[3];
    const float* bproj = (const float*)d_in[4];
    float* out = (float*)d_out;

    float* qkv;
    float* attn;
    cudaGetSymbolAddress((void**)&qkv,  g_qkv);
    cudaGetSymbolAddress((void**)&attn, g_attn);

    const int attn_smem = 68 * (128 + 64 + 64 + 128) * 4;  // 104448 B
    cudaFuncSetAttribute(attn_tf32_kernel,
                         cudaFuncAttributeMaxDynamicSharedMemorySize, attn_smem);

    {   // QKV: [8192,768] @ [2304,768]^T + b
        dim3 grid(2304 / 128, 8192 / 128);
        gemm_tf32_kernel<<<grid, 256>>>(x, Wqkv, bqkv, qkv, 8192, 2304, 768);
    }
    {   // attention
        attn_tf32_kernel<<<768, 128, attn_smem>>>();
    }
    {   // proj: [8192,768] @ [768,768]^T + b
        dim3 grid(768 / 128, 8192 / 128);
        gemm_tf32_kernel<<<grid, 256>>>(attn, Wproj, bproj, out, 8192, 768, 768);
    }
}

// round 3
// speedup vs baseline: 3.9076x; 1.0749x over previous
#include <cuda_runtime.h>
#include <cuda_bf16.h>
#include <cstdint>

// Problem: B=8, N=1024, D=768, H=12, Hd=64
__device__ float g_qkv[8192 * 2304];
__device__ float g_attn[8192 * 768];

// ---------------------------------------------------------------------------
// helpers
// ---------------------------------------------------------------------------
__device__ __forceinline__ uint32_t f2tf(float f) {
    uint32_t u;
    asm("cvt.rna.tf32.f32 %0, %1;" : "=r"(u) : "f"(f));
    return u;
}

__device__ __forceinline__ void mma_tf32(float c[4],
                                         uint32_t a0, uint32_t a1, uint32_t a2, uint32_t a3,
                                         uint32_t b0, uint32_t b1) {
    asm volatile(
        "mma.sync.aligned.m16n8k8.row.col.f32.tf32.tf32.f32 "
        "{%0,%1,%2,%3}, {%4,%5,%6,%7}, {%8,%9}, {%0,%1,%2,%3};"
        : "+f"(c[0]), "+f"(c[1]), "+f"(c[2]), "+f"(c[3])
        : "r"(a0), "r"(a1), "r"(a2), "r"(a3), "r"(b0), "r"(b1));
}

// ldmatrix x4: each 8x4 tile of u32 viewed as 8x8 b16; thread l gets u32
// element (l/4, l%4) of its matrix -> exactly the tf32 mma fragment layout.
__device__ __forceinline__ void ldsm4(uint32_t r[4], uint32_t addr) {
    asm volatile("ldmatrix.sync.aligned.m8n8.x4.shared.b16 {%0,%1,%2,%3}, [%4];"
                 : "=r"(r[0]), "=r"(r[1]), "=r"(r[2]), "=r"(r[3]) : "r"(addr));
}

// ---------------------------------------------------------------------------
// TF32 GEMM: C[M,N] = A[M,K] @ W[N,K]^T + bias[N]
// Block 128x128, BK=32, 256 threads (8 warps as 4x2), warp tile 32x64.
// Double-buffered dynamic smem; ldmatrix fragment loads.
// smem u32 layout: A0[4608] A1[4608] W0[4608] W1[4608]  (LDA=36, pad 4)
// ---------------------------------------------------------------------------
__global__ __launch_bounds__(256, 2) void gemm_tf32_kernel(
    const float* __restrict__ A, const float* __restrict__ W,
    const float* __restrict__ bias, float* __restrict__ C,
    int M, int N, int K)
{
    extern __shared__ uint32_t sm[];
    constexpr int LDA = 36;
    constexpr int STG = 128 * LDA;          // u32 per operand-stage (4608)
    constexpr int STG_B = STG * 4;          // bytes per stage (18432)

    const int tid  = threadIdx.x;
    const int lane = tid & 31;
    const int wrp  = tid >> 5;
    const int wm   = wrp & 3;
    const int wn   = wrp >> 2;
    const int g    = lane >> 2;
    const int tig  = lane & 3;

    const int m0 = blockIdx.y * 128;
    const int n0 = blockIdx.x * 128;

    const int lr  = tid >> 3;           // 0..31
    const int lc4 = (tid & 7) * 4;      // 0..28

    const uint32_t smb = (uint32_t)__cvta_generic_to_shared(sm);
    // ldmatrix lane bases (bytes). A: matrices {a0,a1,a2,a3}
    const uint32_t aBase = smb +
        ((((32 * wm) + (lane & 15)) * LDA + (lane >> 4) * 4) << 2);
    // B (W region starts at byte 2*STG_B): matrices {b0_j, b1_j, b0_j+1, b1_j+1}
    const uint32_t bBase = smb + 2 * STG_B +
        ((((64 * wn) + (lane & 7) + ((lane >> 4) & 1) * 8) * LDA + ((lane >> 3) & 1) * 4) << 2);

    float acc[2][8][4];
    #pragma unroll
    for (int i = 0; i < 2; i++)
        #pragma unroll
        for (int j = 0; j < 8; j++)
            #pragma unroll
            for (int c = 0; c < 4; c++) acc[i][j][c] = 0.0f;

    float4 ra[4], rw[4];
    #pragma unroll
    for (int i = 0; i < 4; i++) {
        const int row = lr + 32 * i;
        ra[i] = *(const float4*)&A[(size_t)(m0 + row) * K + lc4];
        rw[i] = *(const float4*)&W[(size_t)(n0 + row) * K + lc4];
    }
    // store stage 0
    #pragma unroll
    for (int i = 0; i < 4; i++) {
        const int row = lr + 32 * i;
        *(uint4*)&sm[row * LDA + lc4] =
            make_uint4(f2tf(ra[i].x), f2tf(ra[i].y), f2tf(ra[i].z), f2tf(ra[i].w));
        *(uint4*)&sm[2 * STG + row * LDA + lc4] =
            make_uint4(f2tf(rw[i].x), f2tf(rw[i].y), f2tf(rw[i].z), f2tf(rw[i].w));
    }
    __syncthreads();

    const int NK = K >> 5;
    for (int t = 0; t < NK; t++) {
        const int cur = t & 1;
        const int nxt = cur ^ 1;

        if (t + 1 < NK) {
            const int kofs = (t + 1) * 32 + lc4;
            #pragma unroll
            for (int i = 0; i < 4; i++) {
                const int row = lr + 32 * i;
                ra[i] = *(const float4*)&A[(size_t)(m0 + row) * K + kofs];
                rw[i] = *(const float4*)&W[(size_t)(n0 + row) * K + kofs];
            }
        }

        const uint32_t aoff = aBase + cur * STG_B;
        const uint32_t boff = bBase + cur * STG_B;
        #pragma unroll
        for (int ks = 0; ks < 4; ks++) {
            uint32_t a0[4], a1[4];
            ldsm4(a0, aoff + ks * 32);
            ldsm4(a1, aoff + ks * 32 + 16 * LDA * 4);
            #pragma unroll
            for (int jj = 0; jj < 4; jj++) {
                uint32_t b[4];
                ldsm4(b, boff + ks * 32 + jj * 16 * LDA * 4);
                mma_tf32(acc[0][2 * jj],     a0[0], a0[1], a0[2], a0[3], b[0], b[1]);
                mma_tf32(acc[1][2 * jj],     a1[0], a1[1], a1[2], a1[3], b[0], b[1]);
                mma_tf32(acc[0][2 * jj + 1], a0[0], a0[1], a0[2], a0[3], b[2], b[3]);
                mma_tf32(acc[1][2 * jj + 1], a1[0], a1[1], a1[2], a1[3], b[2], b[3]);
            }
        }

        if (t + 1 < NK) {
            #pragma unroll
            for (int i = 0; i < 4; i++) {
                const int row = lr + 32 * i;
                *(uint4*)&sm[nxt * STG + row * LDA + lc4] =
                    make_uint4(f2tf(ra[i].x), f2tf(ra[i].y), f2tf(ra[i].z), f2tf(ra[i].w));
                *(uint4*)&sm[2 * STG + nxt * STG + row * LDA + lc4] =
                    make_uint4(f2tf(rw[i].x), f2tf(rw[i].y), f2tf(rw[i].z), f2tf(rw[i].w));
            }
        }
        __syncthreads();
    }

    #pragma unroll
    for (int j = 0; j < 8; j++) {
        const int col = n0 + 64 * wn + 8 * j + 2 * tig;
        const float b0 = bias[col];
        const float b1 = bias[col + 1];
        #pragma unroll
        for (int i = 0; i < 2; i++) {
            const int row = m0 + 32 * wm + 16 * i + g;
            *(float2*)&C[(size_t)row * N + col] =
                make_float2(acc[i][j][0] + b0, acc[i][j][1] + b1);
            *(float2*)&C[(size_t)(row + 8) * N + col] =
                make_float2(acc[i][j][2] + b0, acc[i][j][3] + b1);
        }
    }
}

// ---------------------------------------------------------------------------
// TF32 flash attention with ldmatrix fragment loads.
// Block: 128 queries of one (b,h), 128 threads (4 warps x 32 q-rows).
// Dynamic smem u32: Qs[128*68] Ks[64*68] Vt[64*68] Ps[128*68]  (LDA=68)
// ---------------------------------------------------------------------------
__global__ __launch_bounds__(128) void attn_tf32_kernel()
{
    extern __shared__ uint32_t sm[];
    constexpr int LDA = 68;
    uint32_t* Qs = sm;                   // off 0
    uint32_t* Ks = Qs + 128 * LDA;       // u32 off 8704  (byte 34816)
    uint32_t* Vt = Ks + 64 * LDA;        // u32 off 13056 (byte 52224)
    uint32_t* Ps = Vt + 64 * LDA;        // u32 off 17408 (byte 69632)

    const int tid  = threadIdx.x;
    const int lane = tid & 31;
    const int wrp  = tid >> 5;
    const int g    = lane >> 2;
    const int tig  = lane & 3;

    const int qtile = blockIdx.x & 7;
    const int bh    = blockIdx.x >> 3;
    const int h     = bh % 12;
    const int b     = bh / 12;
    const int q0    = qtile * 128;
    const int mb    = 32 * wrp;

    const uint32_t smb = (uint32_t)__cvta_generic_to_shared(sm);
    // A-style lane base (Q and P), already including warp row base mb
    const uint32_t qaBase = smb +
        (((mb + (lane & 15)) * LDA + (lane >> 4) * 4) << 2);
    const uint32_t paBase = qaBase + 69632;
    // B-style lane base (K), V base = K + 17408 bytes
    const uint32_t kbBase = smb + 34816 +
        ((((lane & 7) + ((lane >> 4) & 1) * 8) * LDA + ((lane >> 3) & 1) * 4) << 2);
    const uint32_t vbBase = kbBase + 17408;

    // load Q tile [128][64] -> tf32 smem
    #pragma unroll
    for (int it = 0; it < 16; it++) {
        const int e   = tid + it * 128;
        const int row = e >> 4;
        const int c4  = (e & 15) * 4;
        const float4 qv = *(const float4*)&g_qkv[(size_t)(b * 1024 + q0 + row) * 2304 + h * 64 + c4];
        *(uint4*)&Qs[row * LDA + c4] = make_uint4(f2tf(qv.x), f2tf(qv.y), f2tf(qv.z), f2tf(qv.w));
    }

    float O[2][8][4];
    #pragma unroll
    for (int i = 0; i < 2; i++)
        #pragma unroll
        for (int j = 0; j < 8; j++)
            #pragma unroll
            for (int c = 0; c < 4; c++) O[i][j][c] = 0.0f;

    float mrun[2][2], lrun[2][2];
    #pragma unroll
    for (int i = 0; i < 2; i++)
        #pragma unroll
        for (int hf = 0; hf < 2; hf++) { mrun[i][hf] = -1e30f; lrun[i][hf] = 0.0f; }

    for (int kt = 0; kt < 1024; kt += 64) {
        __syncthreads();
        #pragma unroll
        for (int it = 0; it < 8; it++) {
            const int e   = tid + it * 128;
            const int key = e >> 4;
            const int c4  = (e & 15) * 4;
            const size_t base = (size_t)(b * 1024 + kt + key) * 2304 + h * 64 + c4;
            const float4 kv = *(const float4*)&g_qkv[base + 768];
            *(uint4*)&Ks[key * LDA + c4] = make_uint4(f2tf(kv.x), f2tf(kv.y), f2tf(kv.z), f2tf(kv.w));
            const float4 vv = *(const float4*)&g_qkv[base + 1536];
            Vt[(c4 + 0) * LDA + key] = f2tf(vv.x);
            Vt[(c4 + 1) * LDA + key] = f2tf(vv.y);
            Vt[(c4 + 2) * LDA + key] = f2tf(vv.z);
            Vt[(c4 + 3) * LDA + key] = f2tf(vv.w);
        }
        __syncthreads();

        // S = Q @ K^T
        float s[2][8][4];
        #pragma unroll
        for (int i = 0; i < 2; i++)
            #pragma unroll
            for (int j = 0; j < 8; j++)
                #pragma unroll
                for (int c = 0; c < 4; c++) s[i][j][c] = 0.0f;

        #pragma unroll
        for (int ks = 0; ks < 8; ks++) {
            uint32_t a0[4], a1[4];
            ldsm4(a0, qaBase + ks * 32);
            ldsm4(a1, qaBase + ks * 32 + 16 * LDA * 4);
            #pragma unroll
            for (int jj = 0; jj < 4; jj++) {
                uint32_t bfr[4];
                ldsm4(bfr, kbBase + ks * 32 + jj * 16 * LDA * 4);
                mma_tf32(s[0][2 * jj],     a0[0], a0[1], a0[2], a0[3], bfr[0], bfr[1]);
                mma_tf32(s[1][2 * jj],     a1[0], a1[1], a1[2], a1[3], bfr[0], bfr[1]);
                mma_tf32(s[0][2 * jj + 1], a0[0], a0[1], a0[2], a0[3], bfr[2], bfr[3]);
                mma_tf32(s[1][2 * jj + 1], a1[0], a1[1], a1[2], a1[3], bfr[2], bfr[3]);
            }
        }

        // online softmax + write P (tf32) to Ps
        #pragma unroll
        for (int i = 0; i < 2; i++) {
            #pragma unroll
            for (int hf = 0; hf < 2; hf++) {
                float mx = -1e30f;
                #pragma unroll
                for (int j = 0; j < 8; j++) {
                    s[i][j][2 * hf]     *= 0.125f;
                    s[i][j][2 * hf + 1] *= 0.125f;
                    mx = fmaxf(mx, fmaxf(s[i][j][2 * hf], s[i][j][2 * hf + 1]));
                }
                mx = fmaxf(mx, __shfl_xor_sync(0xffffffffu, mx, 1));
                mx = fmaxf(mx, __shfl_xor_sync(0xffffffffu, mx, 2));
                const float nm   = fmaxf(mrun[i][hf], mx);
                const float corr = __expf(mrun[i][hf] - nm);
                mrun[i][hf] = nm;
                float sum = 0.0f;
                #pragma unroll
                for (int j = 0; j < 8; j++) {
                    const float p0 = __expf(s[i][j][2 * hf] - nm);
                    const float p1 = __expf(s[i][j][2 * hf + 1] - nm);
                    s[i][j][2 * hf] = p0;
                    s[i][j][2 * hf + 1] = p1;
                    sum += p0 + p1;
                }
                sum += __shfl_xor_sync(0xffffffffu, sum, 1);
                sum += __shfl_xor_sync(0xffffffffu, sum, 2);
                lrun[i][hf] = lrun[i][hf] * corr + sum;
                #pragma unroll
                for (int j = 0; j < 8; j++) {
                    O[i][j][2 * hf]     *= corr;
                    O[i][j][2 * hf + 1] *= corr;
                }
                const int row = mb + 16 * i + g + 8 * hf;
                #pragma unroll
                for (int j = 0; j < 8; j++) {
                    *(uint2*)&Ps[row * LDA + 8 * j + 2 * tig] =
                        make_uint2(f2tf(s[i][j][2 * hf]), f2tf(s[i][j][2 * hf + 1]));
                }
            }
        }
        __syncwarp();

        // O += P @ V
        #pragma unroll
        for (int ks = 0; ks < 8; ks++) {
            uint32_t a0[4], a1[4];
            ldsm4(a0, paBase + ks * 32);
            ldsm4(a1, paBase + ks * 32 + 16 * LDA * 4);
            #pragma unroll
            for (int jj = 0; jj < 4; jj++) {
                uint32_t bfr[4];
                ldsm4(bfr, vbBase + ks * 32 + jj * 16 * LDA * 4);
                mma_tf32(O[0][2 * jj],     a0[0], a0[1], a0[2], a0[3], bfr[0], bfr[1]);
                mma_tf32(O[1][2 * jj],     a1[0], a1[1], a1[2], a1[3], bfr[0], bfr[1]);
                mma_tf32(O[0][2 * jj + 1], a0[0], a0[1], a0[2], a0[3], bfr[2], bfr[3]);
                mma_tf32(O[1][2 * jj + 1], a1[0], a1[1], a1[2], a1[3], bfr[2], bfr[3]);
            }
        }
    }

    // normalize + store
    #pragma unroll
    for (int i = 0; i < 2; i++) {
        #pragma unroll
        for (int hf = 0; hf < 2; hf++) {
            const float linv = 1.0f / lrun[i][hf];
            const int row = q0 + mb + 16 * i + g + 8 * hf;
            #pragma unroll
            for (int j = 0; j < 8; j++) {
                const int col = h * 64 + 8 * j + 2 * tig;
                *(float2*)&g_attn[(size_t)(b * 1024 + row) * 768 + col] =
                    make_float2(O[i][j][2 * hf] * linv, O[i][j][2 * hf + 1] * linv);
            }
        }
    }
}

// ---------------------------------------------------------------------------
// Launch
// ---------------------------------------------------------------------------
extern "C" void kernel_launch(void* const* d_in, const int* in_sizes, int n_in,
                              void* d_out, int out_size)
{
    const float* x     = (const float*)d_in[0];
    const float* Wqkv  = (const float*)d_in[1];
    const float* bqkv  = (const float*)d_in[2];
    const float* Wproj = (const float*)d_in[3];
    const float* bproj = (const float*)d_in[4];
    float* out = (float*)d_out;

    float* qkv;
    float* attn;
    cudaGetSymbolAddress((void**)&qkv,  g_qkv);
    cudaGetSymbolAddress((void**)&attn, g_attn);

    const int gemm_smem = 4 * 128 * 36 * 4;                 // 73728 B
    const int attn_smem = 68 * (128 + 64 + 64 + 128) * 4;   // 104448 B
    static bool attr_done = false;
    if (!attr_done) {
        cudaFuncSetAttribute(gemm_tf32_kernel,
                             cudaFuncAttributeMaxDynamicSharedMemorySize, gemm_smem);
        cudaFuncSetAttribute(attn_tf32_kernel,
                             cudaFuncAttributeMaxDynamicSharedMemorySize, attn_smem);
        attr_done = true;
    }

    {   // QKV: [8192,768] @ [2304,768]^T + b
        dim3 grid(2304 / 128, 8192 / 128);
        gemm_tf32_kernel<<<grid, 256, gemm_smem>>>(x, Wqkv, bqkv, qkv, 8192, 2304, 768);
    }
    {   // attention
        attn_tf32_kernel<<<768, 128, attn_smem>>>();
    }
    {   // proj: [8192,768] @ [768,768]^T + b
        dim3 grid(768 / 128, 8192 / 128);
        gemm_tf32_kernel<<<grid, 256, gemm_smem>>>(attn, Wproj, bproj, out, 8192, 768, 768);
    }
}

// round 5
// speedup vs baseline: 4.4937x; 1.1500x over previous
#include <cuda_runtime.h>
#include <cuda_bf16.h>
#include <cstdint>

// Problem: B=8, N=1024, D=768, H=12, Hd=64
__device__ float g_qkv[8192 * 2304];    // rounded tf32 bits after QKV gemm
__device__ float g_attn[8192 * 768];    // rounded tf32 bits after attention
__device__ float g_xr[8192 * 768];      // x rounded to tf32-rna
__device__ float g_wqkvr[2304 * 768];   // W_qkv rounded
__device__ float g_wprojr[768 * 768];   // W_proj rounded

// ---------------------------------------------------------------------------
// helpers
// ---------------------------------------------------------------------------
__device__ __forceinline__ uint32_t f2tf(float f) {
    uint32_t u;
    asm("cvt.rna.tf32.f32 %0, %1;" : "=r"(u) : "f"(f));
    return u;
}

__device__ __forceinline__ void mma_tf32(float c[4],
                                         uint32_t a0, uint32_t a1, uint32_t a2, uint32_t a3,
                                         uint32_t b0, uint32_t b1) {
    asm volatile(
        "mma.sync.aligned.m16n8k8.row.col.f32.tf32.tf32.f32 "
        "{%0,%1,%2,%3}, {%4,%5,%6,%7}, {%8,%9}, {%0,%1,%2,%3};"
        : "+f"(c[0]), "+f"(c[1]), "+f"(c[2]), "+f"(c[3])
        : "r"(a0), "r"(a1), "r"(a2), "r"(a3), "r"(b0), "r"(b1));
}

__device__ __forceinline__ void ldsm4(uint32_t r[4], uint32_t addr) {
    asm volatile("ldmatrix.sync.aligned.m8n8.x4.shared.b16 {%0,%1,%2,%3}, [%4];"
                 : "=r"(r[0]), "=r"(r[1]), "=r"(r[2]), "=r"(r[3]) : "r"(addr));
}

__device__ __forceinline__ void cpasync16(uint32_t dst, const void* src) {
    asm volatile("cp.async.cg.shared.global [%0], [%1], 16;" :: "r"(dst), "l"(src));
}
__device__ __forceinline__ void cp_commit() {
    asm volatile("cp.async.commit_group;");
}
template <int N>
__device__ __forceinline__ void cp_wait() {
    asm volatile("cp.async.wait_group %0;" :: "n"(N));
}

__device__ __forceinline__ float fast_exp2(float x) {
    float y;
    asm("ex2.approx.ftz.f32 %0, %1;" : "=f"(y) : "f"(x));
    return y;
}

// ---------------------------------------------------------------------------
// Pre-pass: elementwise round fp32 -> tf32-rna bit pattern
// ---------------------------------------------------------------------------
__global__ __launch_bounds__(256) void round_tf32_kernel(
    const float* __restrict__ in, float* __restrict__ out, int n4)
{
    const int i = blockIdx.x * 256 + threadIdx.x;
    if (i < n4) {
        const float4 v = ((const float4*)in)[i];
        uint4 r;
        r.x = f2tf(v.x); r.y = f2tf(v.y); r.z = f2tf(v.z); r.w = f2tf(v.w);
        ((uint4*)out)[i] = r;
    }
}

// ---------------------------------------------------------------------------
// TF32 GEMM: C[M,N] = A[M,K] @ W[N,K]^T + bias[N]
// Inputs pre-rounded to tf32; raw bits fed to mma.
// Block 128x128, BK=32, 256 threads (8 warps 4x2), warp tile 32x64.
// 3-stage cp.async pipeline; SW128 XOR-swizzled smem; ldmatrix frag loads.
// roundOut: round outputs to tf32-rna (when consumed by a later mma stage).
// ---------------------------------------------------------------------------
__global__ __launch_bounds__(256, 2) void gemm_tf32_kernel(
    const float* __restrict__ A, const float* __restrict__ W,
    const float* __restrict__ bias, float* __restrict__ C,
    int M, int N, int K, int roundOut)
{
    extern __shared__ uint32_t sm[];
    constexpr int STG_B = 32768;

    const int tid  = threadIdx.x;
    const int lane = tid & 31;
    const int wrp  = tid >> 5;
    const int wm   = wrp & 3;
    const int wn   = wrp >> 2;
    const int g    = lane >> 2;
    const int tig  = lane & 3;

    const int m0 = blockIdx.y * 128;
    const int n0 = blockIdx.x * 128;

    const uint32_t smb = (uint32_t)__cvta_generic_to_shared(sm);

    const int row0 = tid >> 3;
    const int cch  = tid & 7;
    const uint32_t dsw = (uint32_t)((cch ^ (row0 & 7)) << 4);
    const float* srcA = A + (size_t)(m0 + row0) * K + cch * 4;
    const float* srcW = W + (size_t)(n0 + row0) * K + cch * 4;

    const int rowA = 32 * wm + (lane & 15);
    const uint32_t rbA = (uint32_t)(rowA * 128);
    const uint32_t rxA = (uint32_t)((rowA & 7) << 4);
    const int hiA = lane >> 4;
    const int rowB = 64 * wn + (lane & 7) + ((lane >> 4) & 1) * 8;
    const uint32_t rbB = (uint32_t)(rowB * 128);
    const uint32_t rxB = (uint32_t)((rowB & 7) << 4);
    const int hiB = (lane >> 3) & 1;

    float acc[2][8][4];
    #pragma unroll
    for (int i = 0; i < 2; i++)
        #pragma unroll
        for (int j = 0; j < 8; j++)
            #pragma unroll
            for (int c = 0; c < 4; c++) acc[i][j][c] = 0.0f;

    const int NK = K >> 5;

    #pragma unroll
    for (int s = 0; s < 2; s++) {
        const uint32_t sb = smb + s * STG_B;
        #pragma unroll
        for (int i = 0; i < 4; i++) {
            const uint32_t d = sb + (uint32_t)((row0 + 32 * i) * 128) + dsw;
            cpasync16(d,         srcA + s * 32 + (size_t)(32 * i) * K);
            cpasync16(d + 16384, srcW + s * 32 + (size_t)(32 * i) * K);
        }
        cp_commit();
    }

    int stage = 0;
    for (int t = 0; t < NK; t++) {
        cp_wait<1>();
        __syncthreads();

        if (t + 2 < NK) {
            const int s = (stage + 2 >= 3) ? stage - 1 : stage + 2;
            const uint32_t sb = smb + s * STG_B;
            const int kofs = (t + 2) * 32;
            #pragma unroll
            for (int i = 0; i < 4; i++) {
                const uint32_t d = sb + (uint32_t)((row0 + 32 * i) * 128) + dsw;
                cpasync16(d,         srcA + kofs + (size_t)(32 * i) * K);
                cpasync16(d + 16384, srcW + kofs + (size_t)(32 * i) * K);
            }
        }
        cp_commit();

        const uint32_t sA = smb + stage * STG_B;
        const uint32_t sB = sA + 16384;
        #pragma unroll
        for (int ks = 0; ks < 4; ks++) {
            uint32_t a0[4], a1[4];
            const uint32_t ca = ((uint32_t)((2 * ks + hiA) << 4)) ^ rxA;
            ldsm4(a0, sA + rbA + ca);
            ldsm4(a1, sA + rbA + ca + 2048);
            const uint32_t cb = ((uint32_t)((2 * ks + hiB) << 4)) ^ rxB;
            #pragma unroll
            for (int jj = 0; jj < 4; jj++) {
                uint32_t b[4];
                ldsm4(b, sB + rbB + jj * 2048 + cb);
                mma_tf32(acc[0][2 * jj],     a0[0], a0[1], a0[2], a0[3], b[0], b[1]);
                mma_tf32(acc[1][2 * jj],     a1[0], a1[1], a1[2], a1[3], b[0], b[1]);
                mma_tf32(acc[0][2 * jj + 1], a0[0], a0[1], a0[2], a0[3], b[2], b[3]);
                mma_tf32(acc[1][2 * jj + 1], a1[0], a1[1], a1[2], a1[3], b[2], b[3]);
            }
        }
        stage = (stage + 1 >= 3) ? 0 : stage + 1;
    }

    #pragma unroll
    for (int j = 0; j < 8; j++) {
        const int col = n0 + 64 * wn + 8 * j + 2 * tig;
        const float b0 = bias[col];
        const float b1 = bias[col + 1];
        #pragma unroll
        for (int i = 0; i < 2; i++) {
            const int row = m0 + 32 * wm + 16 * i + g;
            float v0 = acc[i][j][0] + b0, v1 = acc[i][j][1] + b1;
            float v2 = acc[i][j][2] + b0, v3 = acc[i][j][3] + b1;
            if (roundOut) {
                v0 = __uint_as_float(f2tf(v0));
                v1 = __uint_as_float(f2tf(v1));
                v2 = __uint_as_float(f2tf(v2));
                v3 = __uint_as_float(f2tf(v3));
            }
            *(float2*)&C[(size_t)row * N + col]       = make_float2(v0, v1);
            *(float2*)&C[(size_t)(row + 8) * N + col] = make_float2(v2, v3);
        }
    }
}

// ---------------------------------------------------------------------------
// TF32 flash attention. 128 queries/block, 128 threads (4 warps x 32 q-rows).
// Q/K/V pre-rounded (QKV gemm epilogue); raw bits to mma. P rounded rna.
// smem u32: Qs[128*68] Ks[64*68] Vt[64*68] Ps[128*68] (LDA=68)
// ---------------------------------------------------------------------------
__global__ __launch_bounds__(128, 2) void attn_tf32_kernel()
{
    extern __shared__ uint32_t sm[];
    constexpr int LDA = 68;
    uint32_t* Qs = sm;
    uint32_t* Ks = Qs + 128 * LDA;       // byte 34816
    uint32_t* Vt = Ks + 64 * LDA;        // byte 52224
    uint32_t* Ps = Vt + 64 * LDA;        // byte 69632

    const int tid  = threadIdx.x;
    const int lane = tid & 31;
    const int wrp  = tid >> 5;
    const int g    = lane >> 2;
    const int tig  = lane & 3;

    const int qtile = blockIdx.x & 7;
    const int bh    = blockIdx.x >> 3;
    const int h     = bh % 12;
    const int b     = bh / 12;
    const int q0    = qtile * 128;
    const int mb    = 32 * wrp;

    const uint32_t smb = (uint32_t)__cvta_generic_to_shared(sm);
    const uint32_t qaBase = smb + (((mb + (lane & 15)) * LDA + (lane >> 4) * 4) << 2);
    const uint32_t paBase = qaBase + 69632;
    const uint32_t kbBase = smb + 34816 +
        ((((lane & 7) + ((lane >> 4) & 1) * 8) * LDA + ((lane >> 3) & 1) * 4) << 2);
    const uint32_t vbBase = kbBase + 17408;

    #pragma unroll
    for (int it = 0; it < 16; it++) {
        const int e   = tid + it * 128;
        const int row = e >> 4;
        const int c4  = (e & 15) * 4;
        *(float4*)&Qs[row * LDA + c4] =
            *(const float4*)&g_qkv[(size_t)(b * 1024 + q0 + row) * 2304 + h * 64 + c4];
    }

    float O[2][8][4];
    #pragma unroll
    for (int i = 0; i < 2; i++)
        #pragma unroll
        for (int j = 0; j < 8; j++)
            #pragma unroll
            for (int c = 0; c < 4; c++) O[i][j][c] = 0.0f;

    float mrun[2][2], lrun[2][2];
    #pragma unroll
    for (int i = 0; i < 2; i++)
        #pragma unroll
        for (int hf = 0; hf < 2; hf++) { mrun[i][hf] = -1e30f; lrun[i][hf] = 0.0f; }

    const float SC = 0.18033688011112042f;   // 0.125 * log2(e)

    for (int kt = 0; kt < 1024; kt += 64) {
        __syncthreads();
        #pragma unroll
        for (int it = 0; it < 8; it++) {
            const int e   = tid + it * 128;
            const int key = e >> 4;
            const int c   = e & 15;
            const uint32_t dst = smb + 34816 + (uint32_t)((key * LDA + c * 4) << 2);
            cpasync16(dst, &g_qkv[(size_t)(b * 1024 + kt + key) * 2304 + h * 64 + 768 + c * 4]);
        }
        cp_commit();
        #pragma unroll
        for (int it = 0; it < 8; it++) {
            const int e   = tid + it * 128;
            const int key = e >> 4;
            const int c4  = (e & 15) * 4;
            const float4 vv = *(const float4*)
                &g_qkv[(size_t)(b * 1024 + kt + key) * 2304 + h * 64 + 1536 + c4];
            Vt[(c4 + 0) * LDA + key] = __float_as_uint(vv.x);
            Vt[(c4 + 1) * LDA + key] = __float_as_uint(vv.y);
            Vt[(c4 + 2) * LDA + key] = __float_as_uint(vv.z);
            Vt[(c4 + 3) * LDA + key] = __float_as_uint(vv.w);
        }
        cp_wait<0>();
        __syncthreads();

        float s[2][8][4];
        #pragma unroll
        for (int i = 0; i < 2; i++)
            #pragma unroll
            for (int j = 0; j < 8; j++)
                #pragma unroll
                for (int c = 0; c < 4; c++) s[i][j][c] = 0.0f;

        #pragma unroll
        for (int ks = 0; ks < 8; ks++) {
            uint32_t a0[4], a1[4];
            ldsm4(a0, qaBase + ks * 32);
            ldsm4(a1, qaBase + ks * 32 + 16 * LDA * 4);
            #pragma unroll
            for (int jj = 0; jj < 4; jj++) {
                uint32_t bfr[4];
                ldsm4(bfr, kbBase + ks * 32 + jj * 16 * LDA * 4);
                mma_tf32(s[0][2 * jj],     a0[0], a0[1], a0[2], a0[3], bfr[0], bfr[1]);
                mma_tf32(s[1][2 * jj],     a1[0], a1[1], a1[2], a1[3], bfr[0], bfr[1]);
                mma_tf32(s[0][2 * jj + 1], a0[0], a0[1], a0[2], a0[3], bfr[2], bfr[3]);
                mma_tf32(s[1][2 * jj + 1], a1[0], a1[1], a1[2], a1[3], bfr[2], bfr[3]);
            }
        }

        #pragma unroll
        for (int i = 0; i < 2; i++) {
            #pragma unroll
            for (int hf = 0; hf < 2; hf++) {
                float mx = -1e30f;
                #pragma unroll
                for (int j = 0; j < 8; j++) {
                    s[i][j][2 * hf]     *= SC;
                    s[i][j][2 * hf + 1] *= SC;
                    mx = fmaxf(mx, fmaxf(s[i][j][2 * hf], s[i][j][2 * hf + 1]));
                }
                mx = fmaxf(mx, __shfl_xor_sync(0xffffffffu, mx, 1));
                mx = fmaxf(mx, __shfl_xor_sync(0xffffffffu, mx, 2));
                const float nm   = fmaxf(mrun[i][hf], mx);
                const float corr = fast_exp2(mrun[i][hf] - nm);
                mrun[i][hf] = nm;
                float sum = 0.0f;
                #pragma unroll
                for (int j = 0; j < 8; j++) {
                    const float p0 = fast_exp2(s[i][j][2 * hf] - nm);
                    const float p1 = fast_exp2(s[i][j][2 * hf + 1] - nm);
                    s[i][j][2 * hf] = p0;
                    s[i][j][2 * hf + 1] = p1;
                    sum += p0 + p1;
                }
                sum += __shfl_xor_sync(0xffffffffu, sum, 1);
                sum += __shfl_xor_sync(0xffffffffu, sum, 2);
                lrun[i][hf] = lrun[i][hf] * corr + sum;
                #pragma unroll
                for (int j = 0; j < 8; j++) {
                    O[i][j][2 * hf]     *= corr;
                    O[i][j][2 * hf + 1] *= corr;
                }
                const int row = mb + 16 * i + g + 8 * hf;
                #pragma unroll
                for (int j = 0; j < 8; j++) {
                    *(uint2*)&Ps[row * LDA + 8 * j + 2 * tig] =
                        make_uint2(f2tf(s[i][j][2 * hf]), f2tf(s[i][j][2 * hf + 1]));
                }
            }
        }
        __syncwarp();

        #pragma unroll
        for (int ks = 0; ks < 8; ks++) {
            uint32_t a0[4], a1[4];
            ldsm4(a0, paBase + ks * 32);
            ldsm4(a1, paBase + ks * 32 + 16 * LDA * 4);
            #pragma unroll
            for (int jj = 0; jj < 4; jj++) {
                uint32_t bfr[4];
                ldsm4(bfr, vbBase + ks * 32 + jj * 16 * LDA * 4);
                mma_tf32(O[0][2 * jj],     a0[0], a0[1], a0[2], a0[3], bfr[0], bfr[1]);
                mma_tf32(O[1][2 * jj],     a1[0], a1[1], a1[2], a1[3], bfr[0], bfr[1]);
                mma_tf32(O[0][2 * jj + 1], a0[0], a0[1], a0[2], a0[3], bfr[2], bfr[3]);
                mma_tf32(O[1][2 * jj + 1], a1[0], a1[1], a1[2], a1[3], bfr[2], bfr[3]);
            }
        }
    }

    #pragma unroll
    for (int i = 0; i < 2; i++) {
        #pragma unroll
        for (int hf = 0; hf < 2; hf++) {
            const float linv = 1.0f / lrun[i][hf];
            const int row = q0 + mb + 16 * i + g + 8 * hf;
            #pragma unroll
            for (int j = 0; j < 8; j++) {
                const int col = h * 64 + 8 * j + 2 * tig;
                *(float2*)&g_attn[(size_t)(b * 1024 + row) * 768 + col] =
                    make_float2(__uint_as_float(f2tf(O[i][j][2 * hf] * linv)),
                                __uint_as_float(f2tf(O[i][j][2 * hf + 1] * linv)));
            }
        }
    }
}

// ---------------------------------------------------------------------------
// Launch
// ---------------------------------------------------------------------------
extern "C" void kernel_launch(void* const* d_in, const int* in_sizes, int n_in,
                              void* d_out, int out_size)
{
    const float* x     = (const float*)d_in[0];
    const float* Wqkv  = (const float*)d_in[1];
    const float* bqkv  = (const float*)d_in[2];
    const float* Wproj = (const float*)d_in[3];
    const float* bproj = (const float*)d_in[4];
    float* out = (float*)d_out;

    float *qkv, *attn, *xr, *wqkvr, *wprojr;
    cudaGetSymbolAddress((void**)&qkv,    g_qkv);
    cudaGetSymbolAddress((void**)&attn,   g_attn);
    cudaGetSymbolAddress((void**)&xr,     g_xr);
    cudaGetSymbolAddress((void**)&wqkvr,  g_wqkvr);
    cudaGetSymbolAddress((void**)&wprojr, g_wprojr);

    const int gemm_smem = 3 * 32768;                        // 98304 B
    const int attn_smem = 68 * (128 + 64 + 64 + 128) * 4;   // 104448 B
    static bool attr_done = false;
    if (!attr_done) {
        cudaFuncSetAttribute(gemm_tf32_kernel,
                             cudaFuncAttributeMaxDynamicSharedMemorySize, gemm_smem);
        cudaFuncSetAttribute(attn_tf32_kernel,
                             cudaFuncAttributeMaxDynamicSharedMemorySize, attn_smem);
        attr_done = true;
    }

    // 0) round inputs to tf32-rna
    round_tf32_kernel<<<(8192 * 768 / 4 + 255) / 256, 256>>>(x, xr, 8192 * 768 / 4);
    round_tf32_kernel<<<(2304 * 768 / 4 + 255) / 256, 256>>>(Wqkv, wqkvr, 2304 * 768 / 4);
    round_tf32_kernel<<<(768 * 768 / 4 + 255) / 256, 256>>>(Wproj, wprojr, 768 * 768 / 4);

    {   // QKV: [8192,768] @ [2304,768]^T + b   (round outputs for attention)
        dim3 grid(2304 / 128, 8192 / 128);
        gemm_tf32_kernel<<<grid, 256, gemm_smem>>>(xr, wqkvr, bqkv, qkv, 8192, 2304, 768, 1);
    }
    {   // attention
        attn_tf32_kernel<<<768, 128, attn_smem>>>();
    }
    {   // proj: [8192,768] @ [768,768]^T + b   (final output, no rounding)
        dim3 grid(768 / 128, 8192 / 128);
        gemm_tf32_kernel<<<grid, 256, gemm_smem>>>(attn, wprojr, bproj, out, 8192, 768, 768, 0);
    }
}

// round 6
// speedup vs baseline: 4.8220x; 1.0731x over previous
#include <cuda_runtime.h>
#include <cuda_bf16.h>
#include <cstdint>

// Problem: B=8, N=1024, D=768, H=12, Hd=64
__device__ float g_qkv[8192 * 2304];    // rounded tf32 bits after QKV gemm
__device__ float g_attn[8192 * 768];    // rounded tf32 bits after attention
__device__ float g_xr[8192 * 768];      // x rounded to tf32-rna
__device__ float g_wqkvr[2304 * 768];   // W_qkv rounded
__device__ float g_wprojr[768 * 768];   // W_proj rounded

// ---------------------------------------------------------------------------
// helpers
// ---------------------------------------------------------------------------
__device__ __forceinline__ uint32_t f2tf(float f) {
    uint32_t u;
    asm("cvt.rna.tf32.f32 %0, %1;" : "=r"(u) : "f"(f));
    return u;
}

__device__ __forceinline__ void mma_tf32(float c[4],
                                         const uint32_t a[4],
                                         uint32_t b0, uint32_t b1) {
    asm volatile(
        "mma.sync.aligned.m16n8k8.row.col.f32.tf32.tf32.f32 "
        "{%0,%1,%2,%3}, {%4,%5,%6,%7}, {%8,%9}, {%0,%1,%2,%3};"
        : "+f"(c[0]), "+f"(c[1]), "+f"(c[2]), "+f"(c[3])
        : "r"(a[0]), "r"(a[1]), "r"(a[2]), "r"(a[3]), "r"(b0), "r"(b1));
}

__device__ __forceinline__ void ldsm4(uint32_t r[4], uint32_t addr) {
    asm volatile("ldmatrix.sync.aligned.m8n8.x4.shared.b16 {%0,%1,%2,%3}, [%4];"
                 : "=r"(r[0]), "=r"(r[1]), "=r"(r[2]), "=r"(r[3]) : "r"(addr));
}

__device__ __forceinline__ void cpasync16(uint32_t dst, const void* src) {
    asm volatile("cp.async.cg.shared.global [%0], [%1], 16;" :: "r"(dst), "l"(src));
}
__device__ __forceinline__ void cp_commit() {
    asm volatile("cp.async.commit_group;");
}
template <int N>
__device__ __forceinline__ void cp_wait() {
    asm volatile("cp.async.wait_group %0;" :: "n"(N));
}

__device__ __forceinline__ float fast_exp2(float x) {
    float y;
    asm("ex2.approx.ftz.f32 %0, %1;" : "=f"(y) : "f"(x));
    return y;
}

// ---------------------------------------------------------------------------
// Pre-pass: elementwise round fp32 -> tf32-rna bit pattern
// ---------------------------------------------------------------------------
__global__ __launch_bounds__(256) void round_tf32_kernel(
    const float* __restrict__ in, float* __restrict__ out, int n4)
{
    const int i = blockIdx.x * 256 + threadIdx.x;
    if (i < n4) {
        const float4 v = ((const float4*)in)[i];
        uint4 r;
        r.x = f2tf(v.x); r.y = f2tf(v.y); r.z = f2tf(v.z); r.w = f2tf(v.w);
        ((uint4*)out)[i] = r;
    }
}

// ---------------------------------------------------------------------------
// TF32 GEMM: C[M,N] = A[M,K] @ W[N,K]^T + bias[N]   (unchanged from R5)
// ---------------------------------------------------------------------------
__global__ __launch_bounds__(256, 2) void gemm_tf32_kernel(
    const float* __restrict__ A, const float* __restrict__ W,
    const float* __restrict__ bias, float* __restrict__ C,
    int M, int N, int K, int roundOut)
{
    extern __shared__ uint32_t sm[];
    constexpr int STG_B = 32768;

    const int tid  = threadIdx.x;
    const int lane = tid & 31;
    const int wrp  = tid >> 5;
    const int wm   = wrp & 3;
    const int wn   = wrp >> 2;
    const int g    = lane >> 2;
    const int tig  = lane & 3;

    const int m0 = blockIdx.y * 128;
    const int n0 = blockIdx.x * 128;

    const uint32_t smb = (uint32_t)__cvta_generic_to_shared(sm);

    const int row0 = tid >> 3;
    const int cch  = tid & 7;
    const uint32_t dsw = (uint32_t)((cch ^ (row0 & 7)) << 4);
    const float* srcA = A + (size_t)(m0 + row0) * K + cch * 4;
    const float* srcW = W + (size_t)(n0 + row0) * K + cch * 4;

    const int rowA = 32 * wm + (lane & 15);
    const uint32_t rbA = (uint32_t)(rowA * 128);
    const uint32_t rxA = (uint32_t)((rowA & 7) << 4);
    const int hiA = lane >> 4;
    const int rowB = 64 * wn + (lane & 7) + ((lane >> 4) & 1) * 8;
    const uint32_t rbB = (uint32_t)(rowB * 128);
    const uint32_t rxB = (uint32_t)((rowB & 7) << 4);
    const int hiB = (lane >> 3) & 1;

    float acc[2][8][4];
    #pragma unroll
    for (int i = 0; i < 2; i++)
        #pragma unroll
        for (int j = 0; j < 8; j++)
            #pragma unroll
            for (int c = 0; c < 4; c++) acc[i][j][c] = 0.0f;

    const int NK = K >> 5;

    #pragma unroll
    for (int s = 0; s < 2; s++) {
        const uint32_t sb = smb + s * STG_B;
        #pragma unroll
        for (int i = 0; i < 4; i++) {
            const uint32_t d = sb + (uint32_t)((row0 + 32 * i) * 128) + dsw;
            cpasync16(d,         srcA + s * 32 + (size_t)(32 * i) * K);
            cpasync16(d + 16384, srcW + s * 32 + (size_t)(32 * i) * K);
        }
        cp_commit();
    }

    int stage = 0;
    for (int t = 0; t < NK; t++) {
        cp_wait<1>();
        __syncthreads();

        if (t + 2 < NK) {
            const int s = (stage + 2 >= 3) ? stage - 1 : stage + 2;
            const uint32_t sb = smb + s * STG_B;
            const int kofs = (t + 2) * 32;
            #pragma unroll
            for (int i = 0; i < 4; i++) {
                const uint32_t d = sb + (uint32_t)((row0 + 32 * i) * 128) + dsw;
                cpasync16(d,         srcA + kofs + (size_t)(32 * i) * K);
                cpasync16(d + 16384, srcW + kofs + (size_t)(32 * i) * K);
            }
        }
        cp_commit();

        const uint32_t sA = smb + stage * STG_B;
        const uint32_t sB = sA + 16384;
        #pragma unroll
        for (int ks = 0; ks < 4; ks++) {
            uint32_t a0[4], a1[4];
            const uint32_t ca = ((uint32_t)((2 * ks + hiA) << 4)) ^ rxA;
            ldsm4(a0, sA + rbA + ca);
            ldsm4(a1, sA + rbA + ca + 2048);
            const uint32_t cb = ((uint32_t)((2 * ks + hiB) << 4)) ^ rxB;
            #pragma unroll
            for (int jj = 0; jj < 4; jj++) {
                uint32_t b[4];
                ldsm4(b, sB + rbB + jj * 2048 + cb);
                mma_tf32(acc[0][2 * jj],     a0, b[0], b[1]);
                mma_tf32(acc[1][2 * jj],     a1, b[0], b[1]);
                mma_tf32(acc[0][2 * jj + 1], a0, b[2], b[3]);
                mma_tf32(acc[1][2 * jj + 1], a1, b[2], b[3]);
            }
        }
        stage = (stage + 1 >= 3) ? 0 : stage + 1;
    }

    #pragma unroll
    for (int j = 0; j < 8; j++) {
        const int col = n0 + 64 * wn + 8 * j + 2 * tig;
        const float b0 = bias[col];
        const float b1 = bias[col + 1];
        #pragma unroll
        for (int i = 0; i < 2; i++) {
            const int row = m0 + 32 * wm + 16 * i + g;
            float v0 = acc[i][j][0] + b0, v1 = acc[i][j][1] + b1;
            float v2 = acc[i][j][2] + b0, v3 = acc[i][j][3] + b1;
            if (roundOut) {
                v0 = __uint_as_float(f2tf(v0));
                v1 = __uint_as_float(f2tf(v1));
                v2 = __uint_as_float(f2tf(v2));
                v3 = __uint_as_float(f2tf(v3));
            }
            *(float2*)&C[(size_t)row * N + col]       = make_float2(v0, v1);
            *(float2*)&C[(size_t)(row + 8) * N + col] = make_float2(v2, v3);
        }
    }
}

// ---------------------------------------------------------------------------
// TF32 flash attention v2.
// 256 threads (8 warps x 16 q-rows), 128 queries/block, 64-key tiles.
// Q fragments live in registers; Q smem region reused as P buffer.
// K double-buffered via cp.async; V double-buffered via register-gather
// transpose (coalesced LDG, conflict-free STS.128 along Vt rows).
// smem u32: Qs/Ps[128*68] @0 | Ks[2][64*68] @8704 | Vt[2][64*68] @17408
// ---------------------------------------------------------------------------
__global__ __launch_bounds__(256, 2) void attn_tf32_kernel()
{
    extern __shared__ uint32_t sm[];
    constexpr int LDA = 68;
    constexpr int KS_U32 = 8704;       // Ks base (u32 idx), byte 34816
    constexpr int VT_U32 = 17408;      // Vt base (u32 idx), byte 69632
    constexpr int STG_U32 = 4352;      // per-stage u32 (17408 bytes)
    constexpr int STG_BYTE = 17408;

    const int tid  = threadIdx.x;
    const int lane = tid & 31;
    const int wrp  = tid >> 5;
    const int g    = lane >> 2;
    const int tig  = lane & 3;

    const int qtile = blockIdx.x & 7;
    const int bh    = blockIdx.x >> 3;
    const int h     = bh % 12;
    const int b     = bh / 12;
    const int q0    = qtile * 128;
    const int mb    = 16 * wrp;         // warp's 16 q-rows

    const uint32_t smb = (uint32_t)__cvta_generic_to_shared(sm);
    const uint32_t qaBase = smb + (((mb + (lane & 15)) * LDA + (lane >> 4) * 4) << 2);
    const uint32_t bRow = (((lane & 7) + ((lane >> 4) & 1) * 8) * LDA + ((lane >> 3) & 1) * 4) << 2;
    const uint32_t kbBase = smb + 34816 + bRow;
    const uint32_t vbBase = smb + 69632 + bRow;

    const size_t tokBase = (size_t)(b * 1024) * 2304 + h * 64;

    // ---- stage Q [128][64] to smem, then pull fragments into registers ----
    #pragma unroll
    for (int it = 0; it < 8; it++) {
        const int e   = tid + it * 256;
        const int row = e >> 4;
        const int c4  = (e & 15) * 4;
        *(float4*)&sm[row * LDA + c4] =
            *(const float4*)&g_qkv[tokBase + (size_t)(q0 + row) * 2304 + c4];
    }
    __syncthreads();
    uint32_t qa[8][4];
    #pragma unroll
    for (int ks = 0; ks < 8; ks++) ldsm4(qa[ks], qaBase + ks * 32);
    // Qs region is now free for reuse as Ps (each warp only touches own rows).

    float O[8][4];
    #pragma unroll
    for (int j = 0; j < 8; j++)
        #pragma unroll
        for (int c = 0; c < 4; c++) O[j][c] = 0.0f;
    float mrun[2] = {-1e30f, -1e30f}, lrun[2] = {0.0f, 0.0f};

    const float SC = 0.18033688011112042f;   // 0.125 * log2(e)

    // ---- prologue: K0 via cp.async, V0 gather-transpose ----
    #pragma unroll
    for (int it = 0; it < 4; it++) {
        const int e   = tid + it * 256;
        const int key = e >> 4;
        const int c   = e & 15;
        cpasync16(smb + 34816 + (uint32_t)((key * LDA + c * 4) << 2),
                  &g_qkv[tokBase + (size_t)key * 2304 + 768 + c * 4]);
    }
    cp_commit();
    #pragma unroll
    for (int it = 0; it < 4; it++) {
        const int u  = tid + it * 256;
        const int hd = u & 63;
        const int kg = u >> 6;
        const size_t vb = tokBase + (size_t)(4 * kg) * 2304 + 1536 + hd;
        float4 v;
        v.x = g_qkv[vb];
        v.y = g_qkv[vb + 2304];
        v.z = g_qkv[vb + 4608];
        v.w = g_qkv[vb + 6912];
        *(float4*)&sm[VT_U32 + hd * LDA + 4 * kg] = v;
    }

    for (int t = 0; t < 16; t++) {
        const int cur = t & 1;
        const int nxt = cur ^ 1;
        const bool pf = (t + 1 < 16);

        cp_wait<0>();
        __syncthreads();

        // prefetch next K (async) + issue next-V gather loads
        float4 gv[4];
        if (pf) {
            const size_t nb = tokBase + (size_t)((t + 1) * 64) * 2304;
            #pragma unroll
            for (int it = 0; it < 4; it++) {
                const int e   = tid + it * 256;
                const int key = e >> 4;
                const int c   = e & 15;
                cpasync16(smb + 34816 + (uint32_t)(nxt * STG_BYTE) +
                              (uint32_t)((key * LDA + c * 4) << 2),
                          &g_qkv[nb + (size_t)key * 2304 + 768 + c * 4]);
            }
            cp_commit();
            #pragma unroll
            for (int it = 0; it < 4; it++) {
                const int u  = tid + it * 256;
                const int hd = u & 63;
                const int kg = u >> 6;
                const size_t vb = nb + (size_t)(4 * kg) * 2304 + 1536 + hd;
                gv[it].x = g_qkv[vb];
                gv[it].y = g_qkv[vb + 2304];
                gv[it].z = g_qkv[vb + 4608];
                gv[it].w = g_qkv[vb + 6912];
            }
        }

        // ---- S = Q @ K^T ----
        float s[8][4];
        #pragma unroll
        for (int j = 0; j < 8; j++)
            #pragma unroll
            for (int c = 0; c < 4; c++) s[j][c] = 0.0f;

        const uint32_t kb = kbBase + cur * STG_BYTE;
        #pragma unroll
        for (int ks = 0; ks < 8; ks++) {
            #pragma unroll
            for (int jj = 0; jj < 4; jj++) {
                uint32_t bfr[4];
                ldsm4(bfr, kb + ks * 32 + jj * (16 * LDA * 4));
                mma_tf32(s[2 * jj],     qa[ks], bfr[0], bfr[1]);
                mma_tf32(s[2 * jj + 1], qa[ks], bfr[2], bfr[3]);
            }
        }

        // store next-V transpose (STS.128 along Vt rows, conflict-free)
        if (pf) {
            #pragma unroll
            for (int it = 0; it < 4; it++) {
                const int u  = tid + it * 256;
                const int hd = u & 63;
                const int kg = u >> 6;
                *(float4*)&sm[VT_U32 + nxt * STG_U32 + hd * LDA + 4 * kg] = gv[it];
            }
        }

        // ---- online softmax (exp2 domain) + write P to Ps (= Qs region) ----
        #pragma unroll
        for (int hf = 0; hf < 2; hf++) {
            float mx = -1e30f;
            #pragma unroll
            for (int j = 0; j < 8; j++) {
                s[j][2 * hf]     *= SC;
                s[j][2 * hf + 1] *= SC;
                mx = fmaxf(mx, fmaxf(s[j][2 * hf], s[j][2 * hf + 1]));
            }
            mx = fmaxf(mx, __shfl_xor_sync(0xffffffffu, mx, 1));
            mx = fmaxf(mx, __shfl_xor_sync(0xffffffffu, mx, 2));
            const float nm   = fmaxf(mrun[hf], mx);
            const float corr = fast_exp2(mrun[hf] - nm);
            mrun[hf] = nm;
            float sum = 0.0f;
            #pragma unroll
            for (int j = 0; j < 8; j++) {
                const float p0 = fast_exp2(s[j][2 * hf] - nm);
                const float p1 = fast_exp2(s[j][2 * hf + 1] - nm);
                s[j][2 * hf] = p0;
                s[j][2 * hf + 1] = p1;
                sum += p0 + p1;
            }
            sum += __shfl_xor_sync(0xffffffffu, sum, 1);
            sum += __shfl_xor_sync(0xffffffffu, sum, 2);
            lrun[hf] = lrun[hf] * corr + sum;
            #pragma unroll
            for (int j = 0; j < 8; j++) {
                O[j][2 * hf]     *= corr;
                O[j][2 * hf + 1] *= corr;
            }
            const int row = mb + g + 8 * hf;
            #pragma unroll
            for (int j = 0; j < 8; j++) {
                *(uint2*)&sm[row * LDA + 8 * j + 2 * tig] =
                    make_uint2(f2tf(s[j][2 * hf]), f2tf(s[j][2 * hf + 1]));
            }
        }
        __syncwarp();

        // ---- O += P @ V ----
        const uint32_t vb = vbBase + cur * STG_BYTE;
        #pragma unroll
        for (int ks = 0; ks < 8; ks++) {
            uint32_t pa[4];
            ldsm4(pa, qaBase + ks * 32);
            #pragma unroll
            for (int jj = 0; jj < 4; jj++) {
                uint32_t bfr[4];
                ldsm4(bfr, vb + ks * 32 + jj * (16 * LDA * 4));
                mma_tf32(O[2 * jj],     pa, bfr[0], bfr[1]);
                mma_tf32(O[2 * jj + 1], pa, bfr[2], bfr[3]);
            }
        }
    }

    // ---- normalize + store (rounded for the proj GEMM) ----
    #pragma unroll
    for (int hf = 0; hf < 2; hf++) {
        const float linv = 1.0f / lrun[hf];
        const int row = q0 + mb + g + 8 * hf;
        #pragma unroll
        for (int j = 0; j < 8; j++) {
            const int col = h * 64 + 8 * j + 2 * tig;
            *(float2*)&g_attn[(size_t)(b * 1024 + row) * 768 + col] =
                make_float2(__uint_as_float(f2tf(O[j][2 * hf] * linv)),
                            __uint_as_float(f2tf(O[j][2 * hf + 1] * linv)));
        }
    }
}

// ---------------------------------------------------------------------------
// Launch
// ---------------------------------------------------------------------------
extern "C" void kernel_launch(void* const* d_in, const int* in_sizes, int n_in,
                              void* d_out, int out_size)
{
    const float* x     = (const float*)d_in[0];
    const float* Wqkv  = (const float*)d_in[1];
    const float* bqkv  = (const float*)d_in[2];
    const float* Wproj = (const float*)d_in[3];
    const float* bproj = (const float*)d_in[4];
    float* out = (float*)d_out;

    float *qkv, *attn, *xr, *wqkvr, *wprojr;
    cudaGetSymbolAddress((void**)&qkv,    g_qkv);
    cudaGetSymbolAddress((void**)&attn,   g_attn);
    cudaGetSymbolAddress((void**)&xr,     g_xr);
    cudaGetSymbolAddress((void**)&wqkvr,  g_wqkvr);
    cudaGetSymbolAddress((void**)&wprojr, g_wprojr);

    const int gemm_smem = 3 * 32768;                        // 98304 B
    const int attn_smem = 68 * (128 + 128 + 128) * 4;       // 104448 B
    static bool attr_done = false;
    if (!attr_done) {
        cudaFuncSetAttribute(gemm_tf32_kernel,
                             cudaFuncAttributeMaxDynamicSharedMemorySize, gemm_smem);
        cudaFuncSetAttribute(attn_tf32_kernel,
                             cudaFuncAttributeMaxDynamicSharedMemorySize, attn_smem);
        attr_done = true;
    }

    // 0) round inputs to tf32-rna
    round_tf32_kernel<<<(8192 * 768 / 4 + 255) / 256, 256>>>(x, xr, 8192 * 768 / 4);
    round_tf32_kernel<<<(2304 * 768 / 4 + 255) / 256, 256>>>(Wqkv, wqkvr, 2304 * 768 / 4);
    round_tf32_kernel<<<(768 * 768 / 4 + 255) / 256, 256>>>(Wproj, wprojr, 768 * 768 / 4);

    {   // QKV: [8192,768] @ [2304,768]^T + b   (round outputs for attention)
        dim3 grid(2304 / 128, 8192 / 128);
        gemm_tf32_kernel<<<grid, 256, gemm_smem>>>(xr, wqkvr, bqkv, qkv, 8192, 2304, 768, 1);
    }
    {   // attention
        attn_tf32_kernel<<<768, 256, attn_smem>>>();
    }
    {   // proj: [8192,768] @ [768,768]^T + b   (final output, no rounding)
        dim3 grid(768 / 128, 8192 / 128);
        gemm_tf32_kernel<<<grid, 256, gemm_smem>>>(attn, wprojr, bproj, out, 8192, 768, 768, 0);
    }
}